// round 10
// baseline (speedup 1.0000x reference)
#include <cuda_runtime.h>

// ---------------- scratch (no allocs allowed) ----------------
__device__ float g_EsP[32][8][180];      // moment partials per (batch, m-tile)
__device__ float g_h1 [32 * 32 * 376];   // [b][co][lo], row padded 374->376
__device__ float g_h2 [32 * 64 * 96];    // [b][co][lo], row padded 92->96
__device__ unsigned g_pA[32];            // A1 tiles done per batch (target 8)
__device__ unsigned g_pB[32];            // AB tasks done per batch (target 24)
__device__ unsigned g_pC[32];            // C  tasks done per batch (target 6)

#define NBLK 296
#define NTHR 256

// ---------------- f32x2 helpers ----------------
typedef unsigned long long ull;

__device__ __forceinline__ float2 unpack2(ull v) {
    float2 f; asm("mov.b64 {%0, %1}, %2;" : "=f"(f.x), "=f"(f.y) : "l"(v)); return f;
}
__device__ __forceinline__ ull ffma2(ull a, ull b, ull c) {
    ull d; asm("fma.rn.f32x2 %0, %1, %2, %3;" : "=l"(d) : "l"(a), "l"(b), "l"(c)); return d;
}

// ================= single persistent kernel, dataflow-synchronized =================
// A1 (256 tasks = b x 8 m-tiles): moment partials -> g_EsP, signal g_pA[b].
// AB (768 tasks = b x 24 lo16-tiles): wait g_pA[b]==8; eval 68-col ctx window
//    (8 ch) in smem + conv1 (16 lo x 32 co) -> g_h1, signal g_pB[b].
// C  (192 tasks = b x 2 co-halves x 3 lo-tiles): wait g_pB[b]==24; conv2 -> g_h2,
//    signal g_pC[b]. The 6th finisher runs D (conv3+linear) and resets counters.
__global__ void __launch_bounds__(NTHR, 2) fused_kernel(
        const float* __restrict__ sig,
        const float* __restrict__ wq, const float* __restrict__ bq,
        const float* __restrict__ wk, const float* __restrict__ bk,
        const float* __restrict__ wv, const float* __restrict__ bv,
        const float* __restrict__ w1, const float* __restrict__ b1,
        const float* __restrict__ w2, const float* __restrict__ b2,
        const float* __restrict__ w3, const float* __restrict__ b3,
        const float* __restrict__ wl, const float* __restrict__ bl,
        float* __restrict__ out) {
    extern __shared__ float smbuf[];
    __shared__ float cw[96];    // [0:24)wq [24:48)wk [48:72)wv [72:80)bq [80:88)bk [88:96)bv
    __shared__ float Pm[16];
    __shared__ float flat[176];
    __shared__ unsigned svD;

    int tid  = threadIdx.x;
    int warp = tid >> 5;
    int lane = tid & 31;

    const float QS = 0.02581988897471611f;  // 1/sqrt(1500)
    const float C6 = 0.16666666666666666f;

    if (tid < 24)      cw[tid] = wq[tid];
    else if (tid < 48) cw[tid] = wk[tid - 24];
    else if (tid < 72) cw[tid] = wv[tid - 48];
    else if (tid < 80) cw[tid] = bq[tid - 72];
    else if (tid < 88) cw[tid] = bk[tid - 80];
    else if (tid < 96) cw[tid] = bv[tid - 88];
    __syncthreads();

    // ---------------- Stage A1: moment partials (blocks 0..255) ----------------
    if (blockIdx.x < 256) {
        const int b = blockIdx.x >> 3;
        const int T = blockIdx.x & 7;
        const int mbase = T * 188;
        const int len = (T == 7) ? 184 : 188;
        const float* sigb = sig + b * 1500;

        float* coef = smbuf;              // [20][192]
        float* vv   = smbuf + 20 * 192;   // [9][192], row 8 = ones

        if (tid < 16) {
            int j = tid >> 2, i = tid & 3;
            float s = 0.f;
#pragma unroll
            for (int c = 0; c < 8; c++) {
                float qv = (j < 3) ? cw[c*3 + j] : cw[72 + c];
                float kv = (i < 3) ? cw[24 + c*3 + i] : cw[80 + c];
                s = fmaf(qv, kv, s);
            }
            Pm[tid] = s * QS;
        }
        __syncthreads();

        for (int j = tid; j < len; j += NTHR) {
            int m = mbase + j;
            float xm1 = (m > 0)    ? sigb[m - 1] : 0.f;
            float x0  = sigb[m];
            float xp1 = (m < 1499) ? sigb[m + 1] : 0.f;
            float a0 = fmaf(Pm[0],  xm1, fmaf(Pm[1],  x0, fmaf(Pm[2],  xp1, Pm[3])));
            float a1 = fmaf(Pm[4],  xm1, fmaf(Pm[5],  x0, fmaf(Pm[6],  xp1, Pm[7])));
            float a2 = fmaf(Pm[8],  xm1, fmaf(Pm[9],  x0, fmaf(Pm[10], xp1, Pm[11])));
            float a3 = fmaf(Pm[12], xm1, fmaf(Pm[13], x0, fmaf(Pm[14], xp1, Pm[15])));

            float p1 = fmaf(a3, fmaf(0.5f, a3, 1.f), 1.f);     // 1 + a3 + a3^2/2
            float p0 = fmaf(a3 * a3 * a3, C6, p1);             // + a3^3/6
            float p2 = fmaf(0.5f, a3, 0.5f);
            float q2 = a3 + 1.f;

            float a00 = a0*a0, a01 = a0*a1, a02 = a0*a2;
            float a11 = a1*a1, a12 = a1*a2, a22 = a2*a2;

            coef[ 0*192 + j] = p0;
            coef[ 1*192 + j] = p1 * a0;
            coef[ 2*192 + j] = p1 * a1;
            coef[ 3*192 + j] = p1 * a2;
            coef[ 4*192 + j] = p2 * a00;
            coef[ 5*192 + j] = q2 * a01;
            coef[ 6*192 + j] = q2 * a02;
            coef[ 7*192 + j] = p2 * a11;
            coef[ 8*192 + j] = q2 * a12;
            coef[ 9*192 + j] = p2 * a22;
            coef[10*192 + j] = C6  * a00 * a0;
            coef[11*192 + j] = 0.5f * a00 * a1;
            coef[12*192 + j] = 0.5f * a00 * a2;
            coef[13*192 + j] = 0.5f * a0  * a11;
            coef[14*192 + j] =        a01 * a2;
            coef[15*192 + j] = 0.5f * a0  * a22;
            coef[16*192 + j] = C6  * a11 * a1;
            coef[17*192 + j] = 0.5f * a11 * a2;
            coef[18*192 + j] = 0.5f * a1  * a22;
            coef[19*192 + j] = C6  * a22 * a2;
#pragma unroll
            for (int c = 0; c < 8; c++) {
                vv[c*192 + j] = fmaf(cw[48 + c*3], xm1,
                                 fmaf(cw[49 + c*3], x0,
                                 fmaf(cw[50 + c*3], xp1, cw[88 + c])));
            }
            vv[8*192 + j] = 1.f;
        }
        __syncthreads();

        for (int pair = warp; pair < 180; pair += 8) {
            int t = pair / 9, c = pair % 9;
            const float* cp = coef + t * 192;
            const float* vp = vv   + c * 192;
            float s = 0.f;
            for (int j = lane; j < len; j += 32) s = fmaf(cp[j], vp[j], s);
#pragma unroll
            for (int off = 16; off; off >>= 1) s += __shfl_xor_sync(0xffffffffu, s, off);
            if (lane == 0) g_EsP[b][T][pair] = s;
        }
        __threadfence();
        __syncthreads();
        if (tid == 0) atomicAdd(&g_pA[b], 1u);   // release
    }

    // ---------------- Stage AB: ctx eval + conv1 (768 tasks) ----------------
    {
        float* xs  = smbuf;           // [8][68] = 544 floats
        float* esS = smbuf + 544;     // [180]
        float* ws1 = smbuf + 736;     // 2048 floats (w1)

        __syncthreads();              // A1 smem region retired
        for (int i = tid; i < 2048; i += NTHR) ws1[i] = w1[i];

        int lastb = -1;
        for (int task = blockIdx.x; task < 768; task += NBLK) {
            int b  = task / 24;
            int tp = task % 24;
            const float* sigb = sig + b * 1500;

            if (tid == 0) { while (atomicAdd(&g_pA[b], 0u) < 8u) {} }  // acquire
            __syncthreads();
            __threadfence();

            if (b != lastb) {
                if (tid < 180) {
                    float s = 0.f;
#pragma unroll
                    for (int T = 0; T < 8; T++) s += g_EsP[b][T][tid];
                    esS[tid] = s;
                }
                lastb = b;
            }
            __syncthreads();   // esS ready; prev task's xs readers done

            // evaluate ctx cols [64*tp, 64*tp+68) x 8 channels (h halves of 4)
            if (tid < 136) {
                int j = tid >> 1, h = tid & 1;
                int cb = h * 4;
                int l = 64 * tp + j;
                if (l < 1500) {
                    float y0 = (l > 0)    ? sigb[l - 1] : 0.f;
                    float y1 = sigb[l];
                    float y2 = (l < 1499) ? sigb[l + 1] : 0.f;
                    float u[20];
                    u[0] = 1.f;  u[1] = y0;  u[2] = y1;  u[3] = y2;
                    u[4] = y0*y0; u[5] = y0*y1; u[6] = y0*y2; u[7] = y1*y1; u[8] = y1*y2; u[9] = y2*y2;
                    u[10] = u[4]*y0; u[11] = u[4]*y1; u[12] = u[4]*y2; u[13] = y0*u[7]; u[14] = u[5]*y2;
                    u[15] = y0*u[9]; u[16] = u[7]*y1; u[17] = u[7]*y2; u[18] = y1*u[9]; u[19] = u[9]*y2;

                    float cx0 = 0.f, cx1 = 0.f, cx2 = 0.f, cx3 = 0.f, den = 0.f;
#pragma unroll
                    for (int tt = 0; tt < 20; tt++) {
                        float ut = u[tt];
                        den = fmaf(ut, esS[tt*9 + 8], den);
                        cx0 = fmaf(ut, esS[tt*9 + cb + 0], cx0);
                        cx1 = fmaf(ut, esS[tt*9 + cb + 1], cx1);
                        cx2 = fmaf(ut, esS[tt*9 + cb + 2], cx2);
                        cx3 = fmaf(ut, esS[tt*9 + cb + 3], cx3);
                    }
                    float inv = 1.f / den;
                    xs[(cb + 0) * 68 + j] = cx0 * inv;
                    xs[(cb + 1) * 68 + j] = cx1 * inv;
                    xs[(cb + 2) * 68 + j] = cx2 * inv;
                    xs[(cb + 3) * 68 + j] = cx3 * inv;
                } else {
                    xs[(cb + 0) * 68 + j] = 0.f;
                    xs[(cb + 1) * 68 + j] = 0.f;
                    xs[(cb + 2) * 68 + j] = 0.f;
                    xs[(cb + 3) * 68 + j] = 0.f;
                }
            }
            __syncthreads();

            // conv1: 16 lo x 32 co; half-warps split co range
            {
                int sub  = lane >> 4;
                int lo16 = lane & 15;
                int cob  = sub * 16 + warp * 2;
                int lo   = 16 * tp + lo16;
                const ull* xsu = (const ull*)xs;    // row stride 34
                const ull* wsu = (const ull*)ws1;   // [co][ci][kpair]
                ull acc[2] = {0ull, 0ull};
#pragma unroll
                for (int ci = 0; ci < 8; ci++) {
                    ull x[4];
#pragma unroll
                    for (int kp = 0; kp < 4; kp++) x[kp] = xsu[ci * 34 + 2 * lo16 + kp];
#pragma unroll
                    for (int c2 = 0; c2 < 2; c2++)
#pragma unroll
                        for (int kp = 0; kp < 4; kp++)
                            acc[c2] = ffma2(wsu[(cob + c2) * 32 + ci * 4 + kp], x[kp], acc[c2]);
                }
                if (lo < 374) {
#pragma unroll
                    for (int c2 = 0; c2 < 2; c2++) {
                        float2 f = unpack2(acc[c2]);
                        g_h1[(b * 32 + cob + c2) * 376 + lo] = f.x + f.y + b1[cob + c2];
                    }
                }
            }
            __threadfence();
            __syncthreads();
            if (tid == 0) atomicAdd(&g_pB[b], 1u);   // release
        }
    }

    // ---------------- Stage C: conv2 (192 tasks) + inline D ----------------
    {
        float* xs = smbuf;          // [32][136] = 4352 floats
        float* ws = smbuf + 4352;   // 8192 floats (half of w2)

        for (int task = blockIdx.x; task < 192; task += NBLK) {
            int b   = task / 6;
            int coh = (task / 3) % 2;
            int t   = task % 3;

            if (tid == 0) { while (atomicAdd(&g_pB[b], 0u) < 24u) {} }  // acquire
            __syncthreads();
            __threadfence();

            const float4* w4 = (const float4*)(w2 + coh * 8192);
            float4* ws4 = (float4*)ws;
            for (int i = tid; i < 2048; i += NTHR) ws4[i] = w4[i];
            for (int i = tid; i < 4352; i += NTHR) {
                int ci = i / 136, j = i % 136;
                int gx = 128 * t + j;
                xs[i] = (gx < 374) ? g_h1[(b * 32 + ci) * 376 + gx] : 0.f;
            }
            __syncthreads();

            {
                int lo  = t * 32 + lane;
                int col = warp * 4;
                const ull* xsu = (const ull*)xs;
                const ull* wsu = (const ull*)ws;
                ull acc[4] = {0ull, 0ull, 0ull, 0ull};
                ull xa[4], xb[4];
#pragma unroll
                for (int kp = 0; kp < 4; kp++) xa[kp] = xsu[2 * lane + kp];
#pragma unroll
                for (int ci = 0; ci < 32; ci += 2) {
#pragma unroll
                    for (int kp = 0; kp < 4; kp++) xb[kp] = xsu[(ci + 1) * 68 + 2 * lane + kp];
#pragma unroll
                    for (int j = 0; j < 4; j++)
#pragma unroll
                        for (int kp = 0; kp < 4; kp++)
                            acc[j] = ffma2(wsu[(col + j) * 128 + ci * 4 + kp], xa[kp], acc[j]);
                    if (ci + 2 < 32) {
#pragma unroll
                        for (int kp = 0; kp < 4; kp++) xa[kp] = xsu[(ci + 2) * 68 + 2 * lane + kp];
                    }
#pragma unroll
                    for (int j = 0; j < 4; j++)
#pragma unroll
                        for (int kp = 0; kp < 4; kp++)
                            acc[j] = ffma2(wsu[(col + j) * 128 + (ci + 1) * 4 + kp], xb[kp], acc[j]);
                }
                if (lo < 92) {
                    int cog = coh * 32 + col;
#pragma unroll
                    for (int j = 0; j < 4; j++) {
                        float2 f = unpack2(acc[j]);
                        g_h2[(b * 64 + cog + j) * 96 + lo] = f.x + f.y + b2[cog + j];
                    }
                }
            }
            __threadfence();
            __syncthreads();
            if (tid == 0) svD = atomicAdd(&g_pC[b], 1u) + 1u;
            __syncthreads();

            // ---------------- Stage D (6th C finisher of batch b) ----------------
            if (svD == 6u) {
                __threadfence();   // acquire all 6 slices of g_h2[b]
                if (lane < 22) {
                    float acc = b3[warp];
                    const float* wp = w3 + warp * 512;
#pragma unroll 8
                    for (int ci = 0; ci < 64; ci++) {
                        const float4* xp = (const float4*)(g_h2 + (b * 64 + ci) * 96 + 4 * lane);
                        float4 x0 = xp[0], x1 = xp[1];
                        const float* w = wp + ci * 8;
                        acc += w[0]*x0.x + w[1]*x0.y + w[2]*x0.z + w[3]*x0.w
                             + w[4]*x1.x + w[5]*x1.y + w[6]*x1.z + w[7]*x1.w;
                    }
                    flat[warp * 22 + lane] = acc;
                }
                __syncthreads();

                if (warp < 3) {
                    float s = 0.f;
                    for (int i = lane; i < 176; i += 32) s += wl[warp * 176 + i] * flat[i];
#pragma unroll
                    for (int off = 16; off; off >>= 1) s += __shfl_xor_sync(0xffffffffu, s, off);
                    if (lane == 0) out[b * 3 + warp] = s + bl[warp];
                }
                __syncthreads();
                if (tid == 0) {   // reset for next graph replay
                    atomicExch(&g_pA[b], 0u);
                    atomicExch(&g_pB[b], 0u);
                    atomicExch(&g_pC[b], 0u);
                }
            }
        }
    }
}

// ---------------- launch ----------------
extern "C" void kernel_launch(void* const* d_in, const int* in_sizes, int n_in,
                              void* d_out, int out_size) {
    const float* signal = (const float*)d_in[0];
    const float* wq = (const float*)d_in[1];
    const float* bq = (const float*)d_in[2];
    const float* wk = (const float*)d_in[3];
    const float* bk = (const float*)d_in[4];
    const float* wv = (const float*)d_in[5];
    const float* bv = (const float*)d_in[6];
    const float* w1 = (const float*)d_in[7];
    const float* b1 = (const float*)d_in[8];
    const float* w2 = (const float*)d_in[9];
    const float* b2 = (const float*)d_in[10];
    const float* w3 = (const float*)d_in[11];
    const float* b3 = (const float*)d_in[12];
    const float* wl = (const float*)d_in[13];
    const float* bl = (const float*)d_in[14];
    float* out = (float*)d_out;

    cudaFuncSetAttribute(fused_kernel, cudaFuncAttributeMaxDynamicSharedMemorySize, 50176);
    fused_kernel<<<NBLK, NTHR, 50176>>>(signal, wq, bq, wk, bk, wv, bv,
                                        w1, b1, w2, b2, w3, b3, wl, bl, out);
}

// round 11
// speedup vs baseline: 1.0949x; 1.0949x over previous
#include <cuda_runtime.h>

// ---------------- scratch (no allocs allowed) ----------------
__device__ float g_EsP[32][6][180];      // moment partials per (batch, m-tile)
__device__ float g_h1 [32 * 32 * 376];   // [b][co][lo], row padded 374->376
__device__ float g_h2 [32 * 64 * 96];    // [b][co][lo], row padded 92->96
__device__ unsigned g_bar = 0;           // monotonic grid barrier counter
__device__ unsigned g_pC[32];            // C tasks done per batch (target 6)

#define NBLK 192
#define NTHR 256

// ---------------- f32x2 helpers ----------------
typedef unsigned long long ull;

__device__ __forceinline__ float2 unpack2(ull v) {
    float2 f; asm("mov.b64 {%0, %1}, %2;" : "=f"(f.x), "=f"(f.y) : "l"(v)); return f;
}
__device__ __forceinline__ ull ffma2(ull a, ull b, ull c) {
    ull d; asm("fma.rn.f32x2 %0, %1, %2, %3;" : "=l"(d) : "l"(a), "l"(b), "l"(c)); return d;
}

// grid-wide barrier, replay-safe (counter only grows; cohort = next multiple of NBLK)
__device__ __forceinline__ void grid_barrier() {
    __syncthreads();
    if (threadIdx.x == 0) {
        __threadfence();
        unsigned a = atomicAdd(&g_bar, 1u) + 1u;
        unsigned target = ((a - 1u) / NBLK + 1u) * NBLK;
        while (*(volatile unsigned*)&g_bar < target) { }
        __threadfence();
    }
    __syncthreads();
}

// ================= single persistent kernel, 1 task per block per phase =================
// A1 (192 = b x 6 m-tiles of 250): moment partials -> g_EsP.        [barrier]
// AB (192 = b x 6 lo64-tiles): eval 260-col ctx window + conv1 -> g_h1. [barrier]
// C  (192 = b x 2 co-halves x 3 lo-tiles): conv2 -> g_h2; 6th finisher per batch
//    runs D (conv3 + linear) inline and resets the ticket.
__global__ void __launch_bounds__(NTHR, 2) fused_kernel(
        const float* __restrict__ sig,
        const float* __restrict__ wq, const float* __restrict__ bq,
        const float* __restrict__ wk, const float* __restrict__ bk,
        const float* __restrict__ wv, const float* __restrict__ bv,
        const float* __restrict__ w1, const float* __restrict__ b1,
        const float* __restrict__ w2, const float* __restrict__ b2,
        const float* __restrict__ w3, const float* __restrict__ b3,
        const float* __restrict__ wl, const float* __restrict__ bl,
        float* __restrict__ out) {
    extern __shared__ float smbuf[];
    __shared__ float cw[96];    // [0:24)wq [24:48)wk [48:72)wv [72:80)bq [80:88)bk [88:96)bv
    __shared__ float Pm[16];
    __shared__ float flat[176];
    __shared__ unsigned svD;

    int tid  = threadIdx.x;
    int warp = tid >> 5;
    int lane = tid & 31;

    const float QS = 0.02581988897471611f;  // 1/sqrt(1500)
    const float C6 = 0.16666666666666666f;

    const int b  = blockIdx.x / 6;   // batch for A1/AB/C task
    const int tt6 = blockIdx.x % 6;  // sub-task index within batch

    if (tid < 24)      cw[tid] = wq[tid];
    else if (tid < 48) cw[tid] = wk[tid - 24];
    else if (tid < 72) cw[tid] = wv[tid - 48];
    else if (tid < 80) cw[tid] = bq[tid - 72];
    else if (tid < 88) cw[tid] = bk[tid - 80];
    else if (tid < 96) cw[tid] = bv[tid - 88];
    __syncthreads();

    // ---------------- Phase A1: moment partials (1 task: batch b, tile tt6) ----------------
    {
        const int mbase = tt6 * 250;
        const float* sigb = sig + b * 1500;

        float* coef = smbuf;              // [20][252]
        float* vv   = smbuf + 20 * 252;   // [9][252], row 8 = ones

        if (tid < 16) {
            int j = tid >> 2, i = tid & 3;
            float s = 0.f;
#pragma unroll
            for (int c = 0; c < 8; c++) {
                float qv = (j < 3) ? cw[c*3 + j] : cw[72 + c];
                float kv = (i < 3) ? cw[24 + c*3 + i] : cw[80 + c];
                s = fmaf(qv, kv, s);
            }
            Pm[tid] = s * QS;
        }
        __syncthreads();

        for (int j = tid; j < 250; j += NTHR) {
            int m = mbase + j;
            float xm1 = (m > 0)    ? sigb[m - 1] : 0.f;
            float x0  = sigb[m];
            float xp1 = (m < 1499) ? sigb[m + 1] : 0.f;
            float a0 = fmaf(Pm[0],  xm1, fmaf(Pm[1],  x0, fmaf(Pm[2],  xp1, Pm[3])));
            float a1 = fmaf(Pm[4],  xm1, fmaf(Pm[5],  x0, fmaf(Pm[6],  xp1, Pm[7])));
            float a2 = fmaf(Pm[8],  xm1, fmaf(Pm[9],  x0, fmaf(Pm[10], xp1, Pm[11])));
            float a3 = fmaf(Pm[12], xm1, fmaf(Pm[13], x0, fmaf(Pm[14], xp1, Pm[15])));

            float p1 = fmaf(a3, fmaf(0.5f, a3, 1.f), 1.f);     // 1 + a3 + a3^2/2
            float p0 = fmaf(a3 * a3 * a3, C6, p1);             // + a3^3/6
            float p2 = fmaf(0.5f, a3, 0.5f);
            float q2 = a3 + 1.f;

            float a00 = a0*a0, a01 = a0*a1, a02 = a0*a2;
            float a11 = a1*a1, a12 = a1*a2, a22 = a2*a2;

            coef[ 0*252 + j] = p0;
            coef[ 1*252 + j] = p1 * a0;
            coef[ 2*252 + j] = p1 * a1;
            coef[ 3*252 + j] = p1 * a2;
            coef[ 4*252 + j] = p2 * a00;
            coef[ 5*252 + j] = q2 * a01;
            coef[ 6*252 + j] = q2 * a02;
            coef[ 7*252 + j] = p2 * a11;
            coef[ 8*252 + j] = q2 * a12;
            coef[ 9*252 + j] = p2 * a22;
            coef[10*252 + j] = C6  * a00 * a0;
            coef[11*252 + j] = 0.5f * a00 * a1;
            coef[12*252 + j] = 0.5f * a00 * a2;
            coef[13*252 + j] = 0.5f * a0  * a11;
            coef[14*252 + j] =        a01 * a2;
            coef[15*252 + j] = 0.5f * a0  * a22;
            coef[16*252 + j] = C6  * a11 * a1;
            coef[17*252 + j] = 0.5f * a11 * a2;
            coef[18*252 + j] = 0.5f * a1  * a22;
            coef[19*252 + j] = C6  * a22 * a2;
#pragma unroll
            for (int c = 0; c < 8; c++) {
                vv[c*252 + j] = fmaf(cw[48 + c*3], xm1,
                                 fmaf(cw[49 + c*3], x0,
                                 fmaf(cw[50 + c*3], xp1, cw[88 + c])));
            }
            vv[8*252 + j] = 1.f;
        }
        __syncthreads();

        for (int pair = warp; pair < 180; pair += 8) {
            int t = pair / 9, c = pair % 9;
            const float* cp = coef + t * 252;
            const float* vp = vv   + c * 252;
            float s = 0.f;
            for (int j = lane; j < 250; j += 32) s = fmaf(cp[j], vp[j], s);
#pragma unroll
            for (int off = 16; off; off >>= 1) s += __shfl_xor_sync(0xffffffffu, s, off);
            if (lane == 0) g_EsP[b][tt6][pair] = s;
        }
    }

    grid_barrier();   // g_EsP visible

    // ---------------- Phase AB: ctx eval + conv1 (1 task: batch b, lo-tile tt6) ----------------
    {
        float* xs  = smbuf;           // [8][264] = 2112 floats
        float* esS = smbuf + 2112;    // [180]
        float* ws1 = smbuf + 2304;    // 2048 floats (w1)

        for (int i = tid; i < 2048; i += NTHR) ws1[i] = w1[i];
        if (tid < 180) {
            float s = 0.f;
#pragma unroll
            for (int T = 0; T < 6; T++) s += g_EsP[b][T][tid];
            esS[tid] = s;
        }
        __syncthreads();

        const float* sigb = sig + b * 1500;
        // evaluate ctx cols [256*tt6, 256*tt6+260) x 8 channels (2 halves of 4)
        for (int i = tid; i < 520; i += NTHR) {
            int j = i >> 1, h = i & 1;
            int cb = h * 4;
            int l = 256 * tt6 + j;
            if (l < 1500) {
                float y0 = (l > 0)    ? sigb[l - 1] : 0.f;
                float y1 = sigb[l];
                float y2 = (l < 1499) ? sigb[l + 1] : 0.f;
                float u[20];
                u[0] = 1.f;  u[1] = y0;  u[2] = y1;  u[3] = y2;
                u[4] = y0*y0; u[5] = y0*y1; u[6] = y0*y2; u[7] = y1*y1; u[8] = y1*y2; u[9] = y2*y2;
                u[10] = u[4]*y0; u[11] = u[4]*y1; u[12] = u[4]*y2; u[13] = y0*u[7]; u[14] = u[5]*y2;
                u[15] = y0*u[9]; u[16] = u[7]*y1; u[17] = u[7]*y2; u[18] = y1*u[9]; u[19] = u[9]*y2;

                float cx0 = 0.f, cx1 = 0.f, cx2 = 0.f, cx3 = 0.f, den = 0.f;
#pragma unroll
                for (int t = 0; t < 20; t++) {
                    float ut = u[t];
                    den = fmaf(ut, esS[t*9 + 8], den);
                    cx0 = fmaf(ut, esS[t*9 + cb + 0], cx0);
                    cx1 = fmaf(ut, esS[t*9 + cb + 1], cx1);
                    cx2 = fmaf(ut, esS[t*9 + cb + 2], cx2);
                    cx3 = fmaf(ut, esS[t*9 + cb + 3], cx3);
                }
                float inv = 1.f / den;
                xs[(cb + 0) * 264 + j] = cx0 * inv;
                xs[(cb + 1) * 264 + j] = cx1 * inv;
                xs[(cb + 2) * 264 + j] = cx2 * inv;
                xs[(cb + 3) * 264 + j] = cx3 * inv;
            } else {
                xs[(cb + 0) * 264 + j] = 0.f;
                xs[(cb + 1) * 264 + j] = 0.f;
                xs[(cb + 2) * 264 + j] = 0.f;
                xs[(cb + 3) * 264 + j] = 0.f;
            }
        }
        __syncthreads();

        // conv1: 64 lo x 32 co; warp -> 4 co, lane -> lo_local {lane, lane+32}
        {
            int cob = warp * 4;
            const ull* xsu = (const ull*)xs;    // row stride 132 ull
            const ull* wsu = (const ull*)ws1;   // [co][ci][kpair]
            ull acc[4][2] = {{0ull,0ull},{0ull,0ull},{0ull,0ull},{0ull,0ull}};
#pragma unroll
            for (int ci = 0; ci < 8; ci++) {
                ull x0[4], x1[4];
#pragma unroll
                for (int kp = 0; kp < 4; kp++) {
                    x0[kp] = xsu[ci * 132 + 2 * lane + kp];
                    x1[kp] = xsu[ci * 132 + 2 * (lane + 32) + kp];
                }
#pragma unroll
                for (int co = 0; co < 4; co++) {
#pragma unroll
                    for (int kp = 0; kp < 4; kp++) {
                        ull w = wsu[(cob + co) * 32 + ci * 4 + kp];
                        acc[co][0] = ffma2(w, x0[kp], acc[co][0]);
                        acc[co][1] = ffma2(w, x1[kp], acc[co][1]);
                    }
                }
            }
#pragma unroll
            for (int co = 0; co < 4; co++) {
#pragma unroll
                for (int s = 0; s < 2; s++) {
                    int lo = 64 * tt6 + lane + s * 32;
                    if (lo < 374) {
                        float2 f = unpack2(acc[co][s]);
                        g_h1[(b * 32 + cob + co) * 376 + lo] = f.x + f.y + b1[cob + co];
                    }
                }
            }
        }
    }

    grid_barrier();   // g_h1 visible

    // ---------------- Phase C: conv2 (1 task: batch b, coh, t) + inline D ----------------
    {
        float* xs = smbuf;          // [32][136] = 4352 floats
        float* ws = smbuf + 4352;   // 8192 floats (half of w2)

        const int coh = tt6 / 3;
        const int t   = tt6 % 3;

        const float4* w4 = (const float4*)(w2 + coh * 8192);
        float4* ws4 = (float4*)ws;
        for (int i = tid; i < 2048; i += NTHR) ws4[i] = w4[i];
        for (int i = tid; i < 4352; i += NTHR) {
            int ci = i / 136, j = i % 136;
            int gx = 128 * t + j;
            xs[i] = (gx < 374) ? g_h1[(b * 32 + ci) * 376 + gx] : 0.f;
        }
        __syncthreads();

        {
            int lo  = t * 32 + lane;
            int col = warp * 4;
            const ull* xsu = (const ull*)xs;
            const ull* wsu = (const ull*)ws;
            ull acc[4] = {0ull, 0ull, 0ull, 0ull};
            ull xa[4], xb[4];
#pragma unroll
            for (int kp = 0; kp < 4; kp++) xa[kp] = xsu[2 * lane + kp];
#pragma unroll
            for (int ci = 0; ci < 32; ci += 2) {
#pragma unroll
                for (int kp = 0; kp < 4; kp++) xb[kp] = xsu[(ci + 1) * 68 + 2 * lane + kp];
#pragma unroll
                for (int j = 0; j < 4; j++)
#pragma unroll
                    for (int kp = 0; kp < 4; kp++)
                        acc[j] = ffma2(wsu[(col + j) * 128 + ci * 4 + kp], xa[kp], acc[j]);
                if (ci + 2 < 32) {
#pragma unroll
                    for (int kp = 0; kp < 4; kp++) xa[kp] = xsu[(ci + 2) * 68 + 2 * lane + kp];
                }
#pragma unroll
                for (int j = 0; j < 4; j++)
#pragma unroll
                    for (int kp = 0; kp < 4; kp++)
                        acc[j] = ffma2(wsu[(col + j) * 128 + (ci + 1) * 4 + kp], xb[kp], acc[j]);
            }
            if (lo < 92) {
                int cog = coh * 32 + col;
#pragma unroll
                for (int j = 0; j < 4; j++) {
                    float2 f = unpack2(acc[j]);
                    g_h2[(b * 64 + cog + j) * 96 + lo] = f.x + f.y + b2[cog + j];
                }
            }
        }
        __threadfence();
        __syncthreads();
        if (tid == 0) svD = atomicAdd(&g_pC[b], 1u) + 1u;
        __syncthreads();

        // ---------------- Phase D (6th C finisher of batch b) ----------------
        if (svD == 6u) {
            __threadfence();   // acquire all 6 slices of g_h2[b]
            if (lane < 22) {
                float acc = b3[warp];
                const float* wp = w3 + warp * 512;
#pragma unroll 8
                for (int ci = 0; ci < 64; ci++) {
                    const float4* xp = (const float4*)(g_h2 + (b * 64 + ci) * 96 + 4 * lane);
                    float4 x0 = xp[0], x1 = xp[1];
                    const float* w = wp + ci * 8;
                    acc += w[0]*x0.x + w[1]*x0.y + w[2]*x0.z + w[3]*x0.w
                         + w[4]*x1.x + w[5]*x1.y + w[6]*x1.z + w[7]*x1.w;
                }
                flat[warp * 22 + lane] = acc;
            }
            __syncthreads();

            if (warp < 3) {
                float s = 0.f;
                for (int i = lane; i < 176; i += 32) s += wl[warp * 176 + i] * flat[i];
#pragma unroll
                for (int off = 16; off; off >>= 1) s += __shfl_xor_sync(0xffffffffu, s, off);
                if (lane == 0) out[b * 3 + warp] = s + bl[warp];
            }
            __syncthreads();
            if (tid == 0) atomicExch(&g_pC[b], 0u);   // reset for next replay
        }
    }
}

// ---------------- launch ----------------
extern "C" void kernel_launch(void* const* d_in, const int* in_sizes, int n_in,
                              void* d_out, int out_size) {
    const float* signal = (const float*)d_in[0];
    const float* wq = (const float*)d_in[1];
    const float* bq = (const float*)d_in[2];
    const float* wk = (const float*)d_in[3];
    const float* bk = (const float*)d_in[4];
    const float* wv = (const float*)d_in[5];
    const float* bv = (const float*)d_in[6];
    const float* w1 = (const float*)d_in[7];
    const float* b1 = (const float*)d_in[8];
    const float* w2 = (const float*)d_in[9];
    const float* b2 = (const float*)d_in[10];
    const float* w3 = (const float*)d_in[11];
    const float* b3 = (const float*)d_in[12];
    const float* wl = (const float*)d_in[13];
    const float* bl = (const float*)d_in[14];
    float* out = (float*)d_out;

    cudaFuncSetAttribute(fused_kernel, cudaFuncAttributeMaxDynamicSharedMemorySize, 50176);
    fused_kernel<<<NBLK, NTHR, 50176>>>(signal, wq, bq, wk, bk, wv, bv,
                                        w1, b1, w2, b2, w3, b3, wl, bl, out);
}